// round 15
// baseline (speedup 1.0000x reference)
#include <cuda_runtime.h>

// Problem constants (fixed by the dataset)
#define BATCH 8192
#define HDIM  512
#define DPTH  16
#define WPB   8                 // warps per block
#define NBLK  (BATCH / WPB)     // 1024 CTAs  (<= 148*7 = 1036 slots: ONE wave)

// Per-sample losses (scratch; __device__ global per allocation rules)
__device__ float g_perword[BATCH];

// ---------------------------------------------------------------------------
// Main kernel, single-wave variant. Warp-per-sample; hidden[b] staged in
// warp-private shared memory (frees 16 regs), weight rows loaded one at a
// time (16 load regs in flight). __launch_bounds__(256,7) caps regs at 36 so
// 7 CTAs/SM fit -> all 1024 CTAs resident in one wave (no quantization tail).
// No __syncthreads: warps stay fully decoupled (R8 showed CTA coupling costs
// ~4-5us). Ends with the PDL trigger for the dependent reduce.
// ---------------------------------------------------------------------------
__global__ __launch_bounds__(256, 7) void hs_main_kernel(
    const float* __restrict__ hidden,     // [BATCH, HDIM]
    const int*   __restrict__ target,     // [BATCH]
    const float* __restrict__ weights,    // [V, DPTH, HDIM]
    const float* __restrict__ codes,      // [V, DPTH]
    const int*   __restrict__ lengths)    // [V]
{
    const int warp = threadIdx.x >> 5;
    const int lane = threadIdx.x & 31;
    const int b    = blockIdx.x * WPB + warp;

    __shared__ float sh[WPB][HDIM];       // 16KB static; 7 CTAs -> 112KB/SM

    const int word = target[b];           // broadcast load

    // Stage hidden[b] into this warp's smem slice (4 LDG.128 + 4 STS.128).
    float4*       sdst = reinterpret_cast<float4*>(sh[warp]);
    const float4* hp   = reinterpret_cast<const float4*>(hidden + (size_t)b * HDIM);
    #pragma unroll
    for (int i = 0; i < 4; i++) sdst[lane + 32 * i] = hp[lane + 32 * i];
    __syncwarp();

    const float4* wp =
        reinterpret_cast<const float4*>(weights + (size_t)word * DPTH * HDIM);
    const float4* sh4 = reinterpret_cast<const float4*>(sh[warp]);

    float acc[DPTH];
    #pragma unroll
    for (int d = 0; d < DPTH; d++) {
        float4 a[4];
        #pragma unroll
        for (int i = 0; i < 4; i++) a[i] = wp[(size_t)d * 128 + lane + 32 * i];
        float s = 0.0f;
        #pragma unroll
        for (int i = 0; i < 4; i++) {
            float4 h = sh4[lane + 32 * i];   // conflict-free LDS.128
            s += a[i].x * h.x + a[i].y * h.y + a[i].z * h.z + a[i].w * h.w;
        }
        acc[d] = s;
    }

    // ---- Transposed cross-lane reduction: lane l ends with logit d = l & 15
    #pragma unroll
    for (int i = 0; i < 16; i++)
        acc[i] += __shfl_xor_sync(0xffffffff, acc[i], 16);
    #pragma unroll
    for (int i = 0; i < 8; i++) {
        const bool hi = (lane & 8);
        float send = hi ? acc[i] : acc[i + 8];
        float o = __shfl_xor_sync(0xffffffff, send, 8);
        acc[i] = (hi ? acc[i + 8] : acc[i]) + o;
    }
    #pragma unroll
    for (int i = 0; i < 4; i++) {
        const bool hi = (lane & 4);
        float send = hi ? acc[i] : acc[i + 4];
        float o = __shfl_xor_sync(0xffffffff, send, 4);
        acc[i] = (hi ? acc[i + 4] : acc[i]) + o;
    }
    #pragma unroll
    for (int i = 0; i < 2; i++) {
        const bool hi = (lane & 2);
        float send = hi ? acc[i] : acc[i + 2];
        float o = __shfl_xor_sync(0xffffffff, send, 2);
        acc[i] = (hi ? acc[i + 2] : acc[i]) + o;
    }
    {
        const bool hi = (lane & 1);
        float send = hi ? acc[0] : acc[1];
        float o = __shfl_xor_sync(0xffffffff, send, 1);
        acc[0] = (hi ? acc[1] : acc[0]) + o;
    }

    // ---- BCE-with-logits: lane l handles path node d = l & 15 ----
    const int   d = lane & 15;
    const float x = acc[0];
    const float t = codes[(size_t)word * DPTH + d];   // 64B line, bcast halves
    const int   L = lengths[word];
    float bce = fmaxf(x, 0.0f) - x * t + log1pf(expf(-fabsf(x)));
    float v   = (d < L) ? bce : 0.0f;
    #pragma unroll
    for (int o = 8; o; o >>= 1)       // sum within each 16-lane half
        v += __shfl_xor_sync(0xffffffff, v, o);
    if (lane == 0)
        g_perword[b] = v / (float)L;

    // PDL: let the dependent reduce kernel begin its prologue; its
    // cudaGridDependencySynchronize() still waits for full completion.
    cudaTriggerProgrammaticLaunchCompletion();
}

// ---------------------------------------------------------------------------
// Reduce kernel: deterministic single-CTA mean of the 8192 partials (PDL).
// ---------------------------------------------------------------------------
__global__ __launch_bounds__(1024) void hs_reduce_kernel(float* __restrict__ out)
{
    cudaGridDependencySynchronize();   // primary grid complete + visible

    __shared__ float s[32];
    const int tid = threadIdx.x;
    const float4* p4 = reinterpret_cast<const float4*>(g_perword);
    float acc = 0.0f;
    #pragma unroll
    for (int i = 0; i < (BATCH / 4) / 1024; i++) {   // 2 float4 per thread
        float4 v4 = p4[tid + i * 1024];
        acc += v4.x + v4.y + v4.z + v4.w;
    }
    #pragma unroll
    for (int o = 16; o; o >>= 1)
        acc += __shfl_xor_sync(0xffffffff, acc, o);
    if ((tid & 31) == 0) s[tid >> 5] = acc;
    __syncthreads();
    if (tid < 32) {
        float v = s[tid];
        #pragma unroll
        for (int o = 16; o; o >>= 1)
            v += __shfl_xor_sync(0xffffffff, v, o);
        if (tid == 0) out[0] = v / (float)BATCH;
    }
}

extern "C" void kernel_launch(void* const* d_in, const int* in_sizes, int n_in,
                              void* d_out, int out_size)
{
    const float* hidden  = (const float*)d_in[0];
    const int*   target  = (const int*)  d_in[1];
    const float* weights = (const float*)d_in[2];
    const float* codes   = (const float*)d_in[3];
    const int*   lengths = (const int*)  d_in[4];
    float* out = (float*)d_out;

    hs_main_kernel<<<NBLK, 256>>>(hidden, target, weights, codes, lengths);

    // Dependent launch with PDL: prologue overlaps the main grid's tail.
    cudaLaunchConfig_t cfg = {};
    cfg.gridDim  = dim3(1, 1, 1);
    cfg.blockDim = dim3(1024, 1, 1);
    cfg.dynamicSmemBytes = 0;
    cfg.stream = 0;
    cudaLaunchAttribute attr[1];
    attr[0].id = cudaLaunchAttributeProgrammaticStreamSerialization;
    attr[0].val.programmaticStreamSerializationAllowed = 1;
    cfg.attrs = attr;
    cfg.numAttrs = 1;
    cudaLaunchKernelEx(&cfg, hs_reduce_kernel, out);
}

// round 16
// speedup vs baseline: 1.1296x; 1.1296x over previous
#include <cuda_runtime.h>

// Problem constants (fixed by the dataset)
#define BATCH 8192
#define HDIM  512
#define DPTH  16
#define WPB   8                 // warps per block
#define NBLK  (BATCH / WPB)     // 1024 CTAs
#define RBLK  64                // reduce stage-1 CTAs (1 warp each)

// Scratch (__device__ globals per allocation rules). g_done starts 0 and is
// reset by the last reduce CTA each launch -> clean state every graph replay.
__device__ float g_perword[BATCH];
__device__ float g_partial[RBLK];
__device__ unsigned int g_done;

// ---------------------------------------------------------------------------
// Main kernel: EXACT R6/R14 body (fastest measured main: 39.3us).
// Warp-per-sample, no smem, no __syncthreads. PDL trigger at the end.
// ---------------------------------------------------------------------------
__global__ __launch_bounds__(256) void hs_main_kernel(
    const float* __restrict__ hidden,     // [BATCH, HDIM]
    const int*   __restrict__ target,     // [BATCH]
    const float* __restrict__ weights,    // [V, DPTH, HDIM]
    const float* __restrict__ codes,      // [V, DPTH]
    const int*   __restrict__ lengths)    // [V]
{
    const int warp = threadIdx.x >> 5;
    const int lane = threadIdx.x & 31;
    const int b    = blockIdx.x * WPB + warp;

    const int word = target[b];           // broadcast load

    // hidden[b]: lane takes float4 {lane, lane+32, lane+64, lane+96}
    const float4* hp = reinterpret_cast<const float4*>(hidden + (size_t)b * HDIM);
    float4 h[4];
    #pragma unroll
    for (int i = 0; i < 4; i++) h[i] = hp[lane + 32 * i];

    const float4* wp =
        reinterpret_cast<const float4*>(weights + (size_t)word * DPTH * HDIM);

    float acc[DPTH];
    #pragma unroll
    for (int d = 0; d < DPTH; d += 2) {
        float4 a[4], c[4];
        #pragma unroll
        for (int i = 0; i < 4; i++) a[i] = wp[(size_t)d * 128 + lane + 32 * i];
        #pragma unroll
        for (int i = 0; i < 4; i++) c[i] = wp[(size_t)(d + 1) * 128 + lane + 32 * i];
        float s0 = 0.0f, s1 = 0.0f;
        #pragma unroll
        for (int i = 0; i < 4; i++) {
            s0 += a[i].x * h[i].x + a[i].y * h[i].y + a[i].z * h[i].z + a[i].w * h[i].w;
            s1 += c[i].x * h[i].x + c[i].y * h[i].y + c[i].z * h[i].z + c[i].w * h[i].w;
        }
        acc[d]     = s0;
        acc[d + 1] = s1;
    }

    // ---- Transposed cross-lane reduction: lane l ends with logit d = l & 15
    #pragma unroll
    for (int i = 0; i < 16; i++)
        acc[i] += __shfl_xor_sync(0xffffffff, acc[i], 16);
    #pragma unroll
    for (int i = 0; i < 8; i++) {
        const bool hi = (lane & 8);
        float send = hi ? acc[i] : acc[i + 8];
        float o = __shfl_xor_sync(0xffffffff, send, 8);
        acc[i] = (hi ? acc[i + 8] : acc[i]) + o;
    }
    #pragma unroll
    for (int i = 0; i < 4; i++) {
        const bool hi = (lane & 4);
        float send = hi ? acc[i] : acc[i + 4];
        float o = __shfl_xor_sync(0xffffffff, send, 4);
        acc[i] = (hi ? acc[i + 4] : acc[i]) + o;
    }
    #pragma unroll
    for (int i = 0; i < 2; i++) {
        const bool hi = (lane & 2);
        float send = hi ? acc[i] : acc[i + 2];
        float o = __shfl_xor_sync(0xffffffff, send, 2);
        acc[i] = (hi ? acc[i + 2] : acc[i]) + o;
    }
    {
        const bool hi = (lane & 1);
        float send = hi ? acc[0] : acc[1];
        float o = __shfl_xor_sync(0xffffffff, send, 1);
        acc[0] = (hi ? acc[1] : acc[0]) + o;
    }

    // ---- BCE-with-logits: lane l handles path node d = l & 15 ----
    const int   d = lane & 15;
    const float x = acc[0];
    const float t = codes[(size_t)word * DPTH + d];   // 64B line, bcast halves
    const int   L = lengths[word];
    float bce = fmaxf(x, 0.0f) - x * t + log1pf(expf(-fabsf(x)));
    float v   = (d < L) ? bce : 0.0f;
    #pragma unroll
    for (int o = 8; o; o >>= 1)       // sum within each 16-lane half
        v += __shfl_xor_sync(0xffffffff, v, o);
    if (lane == 0)
        g_perword[b] = v / (float)L;

    cudaTriggerProgrammaticLaunchCompletion();
}

// ---------------------------------------------------------------------------
// Reduce: 64 single-warp CTAs (PDL). Each sums 128 contiguous losses in
// fixed order -> stage-2 partial + release ticket (fence-free pattern, proven
// correct in R8/R11). Last CTA sums the 64 partials in fixed order -> mean.
// ---------------------------------------------------------------------------
__global__ __launch_bounds__(32) void hs_reduce_kernel(float* __restrict__ out)
{
    cudaGridDependencySynchronize();   // primary grid complete + visible

    const int lane = threadIdx.x;
    const int cta  = blockIdx.x;

    // 128 floats per CTA = 32 float4, one per lane.
    const float4* p4 = reinterpret_cast<const float4*>(g_perword) + cta * 32;
    float4 v4 = p4[lane];
    float acc = v4.x + v4.y + v4.z + v4.w;
    #pragma unroll
    for (int o = 16; o; o >>= 1)
        acc += __shfl_xor_sync(0xffffffff, acc, o);

    __shared__ bool is_last;
    if (lane == 0) {
        asm volatile("st.global.cg.f32 [%0], %1;"
                     :: "l"(&g_partial[cta]), "f"(acc) : "memory");
        unsigned int tk;
        asm volatile("atom.release.gpu.global.add.u32 %0, [%1], %2;"
                     : "=r"(tk) : "l"(&g_done), "r"(1u) : "memory");
        is_last = (tk == RBLK - 1);
    }
    __syncwarp();
    if (!is_last) return;

    // Last CTA: fixed-order sum of the 64 stage-2 partials.
    if (lane == 0) g_done = 0;         // reset for next graph replay
    float s = __ldcg(&g_partial[lane]) + __ldcg(&g_partial[lane + 32]);
    #pragma unroll
    for (int o = 16; o; o >>= 1)
        s += __shfl_xor_sync(0xffffffff, s, o);
    if (lane == 0) out[0] = s / (float)BATCH;
}

extern "C" void kernel_launch(void* const* d_in, const int* in_sizes, int n_in,
                              void* d_out, int out_size)
{
    const float* hidden  = (const float*)d_in[0];
    const int*   target  = (const int*)  d_in[1];
    const float* weights = (const float*)d_in[2];
    const float* codes   = (const float*)d_in[3];
    const int*   lengths = (const int*)  d_in[4];
    float* out = (float*)d_out;

    hs_main_kernel<<<NBLK, 256>>>(hidden, target, weights, codes, lengths);

    // Dependent launch with PDL: prologue overlaps the main grid's tail.
    cudaLaunchConfig_t cfg = {};
    cfg.gridDim  = dim3(RBLK, 1, 1);
    cfg.blockDim = dim3(32, 1, 1);
    cfg.dynamicSmemBytes = 0;
    cfg.stream = 0;
    cudaLaunchAttribute attr[1];
    attr[0].id = cudaLaunchAttributeProgrammaticStreamSerialization;
    attr[0].val.programmaticStreamSerializationAllowed = 1;
    cfg.attrs = attr;
    cfg.numAttrs = 1;
    cudaLaunchKernelEx(&cfg, hs_reduce_kernel, out);
}